// round 2
// baseline (speedup 1.0000x reference)
#include <cuda_runtime.h>

#define NNODES  50000
#define NPAD    50048      // multiple of 128
#define NEDGE   500000
#define DIM     128
#define DIM2    256
#define NLAYERS 5
#define NGRAPH  128

// ---------------- scratch (static device globals; zero-initialized) ----------------
__device__ float g_h [(size_t)NPAD * DIM];    // current node features h
__device__ float g_z [(size_t)NPAD * DIM];    // z = h + agg   (also reused as z2)
__device__ float g_z1[(size_t)NPAD * DIM2];   // pre-BN hidden (N x 256)
__device__ float g_sum1[DIM2], g_sq1[DIM2], g_aff1[2 * DIM2];  // BN1 stats/affine
__device__ float g_sum2[DIM ], g_sq2[DIM ], g_aff2[2 * DIM ];  // BN2 stats/affine

// ---------------- layer-0 init: h = atom_emb[x]; z = h ----------------
__global__ void k_init(const int* __restrict__ x, const float* __restrict__ atom_emb) {
    int i = blockIdx.x * blockDim.x + threadIdx.x;          // over NNODES*32
    if (i >= NNODES * 32) return;
    int n = i >> 5, c = (i & 31) * 4;
    int a = __ldg(x + n);
    float4 v = *(const float4*)(atom_emb + (size_t)a * DIM + c);
    *(float4*)(g_h + (size_t)n * DIM + c) = v;
    *(float4*)(g_z + (size_t)n * DIM + c) = v;
}

// ---------------- message passing: z[dst] += relu(h[src] + bond_emb[attr]) ----------------
__global__ void k_scatter(const int* __restrict__ src, const int* __restrict__ dst,
                          const int* __restrict__ eattr, const float* __restrict__ bond_emb) {
    int e = blockIdx.x * 8 + (threadIdx.x >> 5);
    if (e >= NEDGE) return;
    int lane = threadIdx.x & 31;
    int s = __ldg(src + e), d = __ldg(dst + e), a = __ldg(eattr + e);
    float4 hv = *(const float4*)(g_h + (size_t)s * DIM + lane * 4);
    float4 ev = *(const float4*)(bond_emb + (size_t)a * DIM + lane * 4);
    float* p = g_z + (size_t)d * DIM + lane * 4;
    atomicAdd(p + 0, fmaxf(hv.x + ev.x, 0.f));
    atomicAdd(p + 1, fmaxf(hv.y + ev.y, 0.f));
    atomicAdd(p + 2, fmaxf(hv.z + ev.z, 0.f));
    atomicAdd(p + 3, fmaxf(hv.w + ev.w, 0.f));
}

// ---------------- zero BN accumulators ----------------
__global__ void k_zero_stats() {
    int t = threadIdx.x;
    if (t < DIM2) { g_sum1[t] = 0.f; g_sq1[t] = 0.f; }
    if (t < DIM)  { g_sum2[t] = 0.f; g_sq2[t] = 0.f; }
}

// ---------------- SGEMM: C[NPAD x NC] = A[NPAD x K] @ Bw[K x NC] + bias ----------------
// BM=128, BN=64, BK=16, 256 threads, 8x4 thread tile.
// If AFF: A elements are transformed a' = relu(a*scale[k] + shift[k]) on load (fused BN+ReLU).
// Epilogue accumulates per-column sum / sumsq (masked to rows < NNODES) for the next BN.
template<int K, int NC, bool AFF>
__global__ void __launch_bounds__(256)
k_gemm(const float* __restrict__ A, const float* __restrict__ Bw,
       const float* __restrict__ bias, const float* __restrict__ aff,
       float* __restrict__ C, float* __restrict__ gsum, float* __restrict__ gsq) {
    __shared__ float As[16][132];            // padded: keeps 16B alignment, mild conflicts
    __shared__ float Bs[16][64];
    __shared__ float sred[2][16][64];
    __shared__ float saff[2 * K];

    const int tid = threadIdx.x;
    const int tx  = tid & 15, ty = tid >> 4;
    const int bm0 = blockIdx.x * 128, bn0 = blockIdx.y * 64;
    const int arow = tid >> 1, ak = (tid & 1) * 8;    // A loads: 2 float4 per thread
    const int brow = tid >> 4, bc4 = (tid & 15) * 4;  // B loads: 1 float4 per thread

    if (AFF) {
        for (int t = tid; t < 2 * K; t += 256) saff[t] = aff[t];
        __syncthreads();   // FIX: saff is consumed by other threads in iteration k0=0
    }

    float acc[8][4];
    #pragma unroll
    for (int m = 0; m < 8; m++)
        #pragma unroll
        for (int n = 0; n < 4; n++) acc[m][n] = 0.f;

    const float* Aptr = A  + (size_t)(bm0 + arow) * K + ak;
    const float* Bptr = Bw + (size_t)brow * NC + bn0 + bc4;

    for (int k0 = 0; k0 < K; k0 += 16) {
        float4 a0 = *(const float4*)(Aptr + k0);
        float4 a1 = *(const float4*)(Aptr + k0 + 4);
        if (AFF) {
            const float* sc = saff + k0 + ak;
            const float* sh = saff + K + k0 + ak;
            a0.x = fmaxf(fmaf(a0.x, sc[0], sh[0]), 0.f);
            a0.y = fmaxf(fmaf(a0.y, sc[1], sh[1]), 0.f);
            a0.z = fmaxf(fmaf(a0.z, sc[2], sh[2]), 0.f);
            a0.w = fmaxf(fmaf(a0.w, sc[3], sh[3]), 0.f);
            a1.x = fmaxf(fmaf(a1.x, sc[4], sh[4]), 0.f);
            a1.y = fmaxf(fmaf(a1.y, sc[5], sh[5]), 0.f);
            a1.z = fmaxf(fmaf(a1.z, sc[6], sh[6]), 0.f);
            a1.w = fmaxf(fmaf(a1.w, sc[7], sh[7]), 0.f);
        }
        // transposed store into As
        As[ak + 0][arow] = a0.x;  As[ak + 1][arow] = a0.y;
        As[ak + 2][arow] = a0.z;  As[ak + 3][arow] = a0.w;
        As[ak + 4][arow] = a1.x;  As[ak + 5][arow] = a1.y;
        As[ak + 6][arow] = a1.z;  As[ak + 7][arow] = a1.w;

        float4 bv = *(const float4*)(Bptr + (size_t)k0 * NC);
        *(float4*)&Bs[brow][bc4] = bv;
        __syncthreads();

        #pragma unroll
        for (int kk = 0; kk < 16; kk++) {
            float ar[8], br[4];
            *(float4*)&ar[0] = *(const float4*)&As[kk][ty * 8];
            *(float4*)&ar[4] = *(const float4*)&As[kk][ty * 8 + 4];
            *(float4*)&br[0] = *(const float4*)&Bs[kk][tx * 4];
            #pragma unroll
            for (int m = 0; m < 8; m++)
                #pragma unroll
                for (int n = 0; n < 4; n++)
                    acc[m][n] = fmaf(ar[m], br[n], acc[m][n]);
        }
        __syncthreads();
    }

    // epilogue: bias add, store, per-column stats (masked to real rows)
    float4 bvq = *(const float4*)(bias + bn0 + (tx << 2));
    float psum[4] = {0.f, 0.f, 0.f, 0.f}, psq[4] = {0.f, 0.f, 0.f, 0.f};
    #pragma unroll
    for (int m = 0; m < 8; m++) {
        int row = bm0 + ty * 8 + m;
        float4 v;
        v.x = acc[m][0] + bvq.x; v.y = acc[m][1] + bvq.y;
        v.z = acc[m][2] + bvq.z; v.w = acc[m][3] + bvq.w;
        *(float4*)(C + (size_t)row * NC + bn0 + (tx << 2)) = v;
        if (row < NNODES) {
            psum[0] += v.x; psq[0] += v.x * v.x;
            psum[1] += v.y; psq[1] += v.y * v.y;
            psum[2] += v.z; psq[2] += v.z * v.z;
            psum[3] += v.w; psq[3] += v.w * v.w;
        }
    }
    #pragma unroll
    for (int n = 0; n < 4; n++) {
        sred[0][ty][(tx << 2) + n] = psum[n];
        sred[1][ty][(tx << 2) + n] = psq[n];
    }
    __syncthreads();
    if (tid < 64) {
        float s = 0.f, q = 0.f;
        #pragma unroll
        for (int i = 0; i < 16; i++) { s += sred[0][i][tid]; q += sred[1][i][tid]; }
        atomicAdd(gsum + bn0 + tid, s);
        atomicAdd(gsq  + bn0 + tid, q);
    }
}

// ---------------- BN stats -> affine (scale, shift) ----------------
__global__ void k_finalize(const float* __restrict__ gsum, const float* __restrict__ gsq,
                           const float* __restrict__ gamma, const float* __restrict__ beta,
                           float* __restrict__ aff, int ncols) {
    int c = threadIdx.x;
    if (c >= ncols) return;
    const float invn = 1.0f / (float)NNODES;
    float mu  = gsum[c] * invn;
    float var = fmaxf(gsq[c] * invn - mu * mu, 0.f);
    float sc  = rsqrtf(var + 1e-5f) * gamma[c];
    aff[c]         = sc;
    aff[ncols + c] = beta[c] - mu * sc;
}

// ---------------- apply BN2 (+optional ReLU): h = bn(z2); z = h ----------------
__global__ void k_bnapply(int relu) {
    int i = blockIdx.x * blockDim.x + threadIdx.x;
    if (i >= NNODES * 32) return;
    int n = i >> 5, c = (i & 31) * 4;
    float4 v  = *(const float4*)(g_z + (size_t)n * DIM + c);
    float4 sc = *(const float4*)(g_aff2 + c);
    float4 sh = *(const float4*)(g_aff2 + DIM + c);
    v.x = fmaf(v.x, sc.x, sh.x);
    v.y = fmaf(v.y, sc.y, sh.y);
    v.z = fmaf(v.z, sc.z, sh.z);
    v.w = fmaf(v.w, sc.w, sh.w);
    if (relu) {
        v.x = fmaxf(v.x, 0.f); v.y = fmaxf(v.y, 0.f);
        v.z = fmaxf(v.z, 0.f); v.w = fmaxf(v.w, 0.f);
    }
    *(float4*)(g_h + (size_t)n * DIM + c) = v;
    *(float4*)(g_z + (size_t)n * DIM + c) = v;
}

// ---------------- output: zero xpool region ----------------
__global__ void k_zero_out(float* __restrict__ out) {
    int i = blockIdx.x * blockDim.x + threadIdx.x;
    if (i < NGRAPH * DIM) out[i] = 0.f;
}

// ---------------- output: xpool = segment_sum(h, batch); copy h ----------------
__global__ void k_pool(const int* __restrict__ batch, float* __restrict__ out) {
    int i = blockIdx.x * blockDim.x + threadIdx.x;
    if (i >= NNODES * 32) return;
    int n = i >> 5, c = (i & 31) * 4;
    float4 v = *(const float4*)(g_h + (size_t)n * DIM + c);
    *(float4*)(out + (size_t)NGRAPH * DIM + (size_t)n * DIM + c) = v;   // h output
    int b = __ldg(batch + n);
    float* p = out + (size_t)b * DIM + c;
    atomicAdd(p + 0, v.x); atomicAdd(p + 1, v.y);
    atomicAdd(p + 2, v.z); atomicAdd(p + 3, v.w);
}

// ---------------- launch ----------------
extern "C" void kernel_launch(void* const* d_in, const int* in_sizes, int n_in,
                              void* d_out, int out_size) {
    const int*   batch    = (const int*)  d_in[0];
    const int*   x        = (const int*)  d_in[1];
    const int*   eidx     = (const int*)  d_in[2];
    const int*   eattr    = (const int*)  d_in[3];
    const float* atom_emb = (const float*)d_in[4];
    const float* bond_emb = (const float*)d_in[5];
    const float* W1       = (const float*)d_in[6];
    const float* b1       = (const float*)d_in[7];
    const float* g1       = (const float*)d_in[8];
    const float* be1      = (const float*)d_in[9];
    const float* W2       = (const float*)d_in[10];
    const float* b2       = (const float*)d_in[11];
    const float* gbn      = (const float*)d_in[12];
    const float* bbn      = (const float*)d_in[13];
    float* out = (float*)d_out;

    float *p_z, *p_z1, *p_sum1, *p_sq1, *p_aff1, *p_sum2, *p_sq2, *p_aff2;
    cudaGetSymbolAddress((void**)&p_z,    g_z);
    cudaGetSymbolAddress((void**)&p_z1,   g_z1);
    cudaGetSymbolAddress((void**)&p_sum1, g_sum1);
    cudaGetSymbolAddress((void**)&p_sq1,  g_sq1);
    cudaGetSymbolAddress((void**)&p_aff1, g_aff1);
    cudaGetSymbolAddress((void**)&p_sum2, g_sum2);
    cudaGetSymbolAddress((void**)&p_sq2,  g_sq2);
    cudaGetSymbolAddress((void**)&p_aff2, g_aff2);

    const int* src = eidx;
    const int* dst = eidx + NEDGE;

    const int ELEM_GRID = (NNODES * 32 + 255) / 256;

    k_init<<<ELEM_GRID, 256>>>(x, atom_emb);

    for (int i = 0; i < NLAYERS; i++) {
        k_zero_stats<<<1, 256>>>();
        k_scatter<<<(NEDGE + 7) / 8, 256>>>(src, dst, eattr, bond_emb);
        k_gemm<DIM, DIM2, false><<<dim3(NPAD / 128, DIM2 / 64), 256>>>(
            p_z, W1 + (size_t)i * DIM * DIM2, b1 + (size_t)i * DIM2, nullptr,
            p_z1, p_sum1, p_sq1);
        k_finalize<<<1, DIM2>>>(p_sum1, p_sq1, g1 + (size_t)i * DIM2, be1 + (size_t)i * DIM2,
                                p_aff1, DIM2);
        k_gemm<DIM2, DIM, true><<<dim3(NPAD / 128, DIM / 64), 256>>>(
            p_z1, W2 + (size_t)i * DIM2 * DIM, b2 + (size_t)i * DIM, p_aff1,
            p_z, p_sum2, p_sq2);
        k_finalize<<<1, DIM>>>(p_sum2, p_sq2, gbn + (size_t)i * DIM, bbn + (size_t)i * DIM,
                               p_aff2, DIM);
        k_bnapply<<<ELEM_GRID, 256>>>(i < NLAYERS - 1 ? 1 : 0);
    }

    k_zero_out<<<(NGRAPH * DIM + 255) / 256, 256>>>(out);
    k_pool<<<ELEM_GRID, 256>>>(batch, out);
}

// round 3
// speedup vs baseline: 1.3316x; 1.3316x over previous
#include <cuda_runtime.h>

#define NNODES  50000
#define NPAD    50048      // multiple of 128
#define NEDGE   500000
#define DIM     128
#define DIM2    256
#define NLAYERS 5
#define NGRAPH  128

// ---------------- scratch (static device globals; zero-initialized) ----------------
__device__ float g_h [(size_t)NPAD * DIM];    // current node features h
__device__ float g_z [(size_t)NPAD * DIM];    // z = h + agg   (also reused as z2)
__device__ float g_z1[(size_t)NPAD * DIM2];   // pre-BN hidden (N x 256)
__device__ float g_sum1[DIM2], g_sq1[DIM2], g_aff1[2 * DIM2];  // BN1 stats/affine
__device__ float g_sum2[DIM ], g_sq2[DIM ], g_aff2[2 * DIM ];  // BN2 stats/affine

__device__ __forceinline__ void red_add_v4(float* p, float4 v) {
    asm volatile("red.global.add.v4.f32 [%0], {%1, %2, %3, %4};"
                 :: "l"(p), "f"(v.x), "f"(v.y), "f"(v.z), "f"(v.w) : "memory");
}

// ---------------- layer-0 init: h = atom_emb[x]; z = h ----------------
__global__ void k_init(const int* __restrict__ x, const float* __restrict__ atom_emb) {
    int i = blockIdx.x * blockDim.x + threadIdx.x;          // over NNODES*32
    if (i >= NNODES * 32) return;
    int n = i >> 5, c = (i & 31) * 4;
    int a = __ldg(x + n);
    float4 v = *(const float4*)(atom_emb + (size_t)a * DIM + c);
    *(float4*)(g_h + (size_t)n * DIM + c) = v;
    *(float4*)(g_z + (size_t)n * DIM + c) = v;
}

// ---------------- message passing: z[dst] += relu(h[src] + bond_emb[attr]) ----------------
__global__ void k_scatter(const int* __restrict__ src, const int* __restrict__ dst,
                          const int* __restrict__ eattr, const float* __restrict__ bond_emb) {
    int e = blockIdx.x * 8 + (threadIdx.x >> 5);
    if (e >= NEDGE) return;
    int lane = threadIdx.x & 31;
    int s = __ldg(src + e), d = __ldg(dst + e), a = __ldg(eattr + e);
    float4 hv = *(const float4*)(g_h + (size_t)s * DIM + lane * 4);
    float4 ev = *(const float4*)(bond_emb + (size_t)a * DIM + lane * 4);
    float4 m;
    m.x = fmaxf(hv.x + ev.x, 0.f);
    m.y = fmaxf(hv.y + ev.y, 0.f);
    m.z = fmaxf(hv.z + ev.z, 0.f);
    m.w = fmaxf(hv.w + ev.w, 0.f);
    red_add_v4(g_z + (size_t)d * DIM + lane * 4, m);
}

// ---------------- zero BN accumulators ----------------
__global__ void k_zero_stats() {
    int t = threadIdx.x;
    if (t < DIM2) { g_sum1[t] = 0.f; g_sq1[t] = 0.f; }
    if (t < DIM)  { g_sum2[t] = 0.f; g_sq2[t] = 0.f; }
}

// ---------------- SGEMM: C[NPAD x NC] = A[NPAD x K] @ Bw[K x NC] + bias ----------------
// BM=128, BN=128, BK=16, 256 threads, 8x8 thread tile, double-buffered smem.
// If AFF: A elements are transformed a' = relu(a*scale[k] + shift[k]) on load.
// Epilogue accumulates per-column sum / sumsq (masked to rows < NNODES).
// Shared layout (floats): As[2][16][132] @0 (4224) | Bs[2][16][128] @4224 (4096) | saff @8320 (<=512)
// Stats staging reuses As region after the main loop.
template<int K, int NC, bool AFF>
__global__ void __launch_bounds__(256)
k_gemm(const float* __restrict__ A, const float* __restrict__ Bw,
       const float* __restrict__ bias, const float* __restrict__ aff,
       float* __restrict__ C, float* __restrict__ gsum, float* __restrict__ gsq) {
    __shared__ float smem[4224 + 4096 + 512];
    float* saff = smem + 8320;

    const int tid = threadIdx.x;
    const int tx  = tid & 15, ty = tid >> 4;
    const int bm0 = blockIdx.x * 128, bn0 = blockIdx.y * 128;

    // A loader: id = tid (+256): arow = id>>2 (0..63, then +64), ac4 = id&3
    const int a_row = tid >> 2;
    const int a_c4  = (tid & 3) * 4;
    // B loader: id = tid (+256): brow = id>>5 (0..7, then +8), bc4 = id&31
    const int b_row = tid >> 5;
    const int b_c   = (tid & 31) * 4;

    if (AFF) {
        for (int t = tid; t < 2 * K; t += 256) saff[t] = aff[t];
        __syncthreads();
    }

    float acc[8][8];
    #pragma unroll
    for (int m = 0; m < 8; m++)
        #pragma unroll
        for (int n = 0; n < 8; n++) acc[m][n] = 0.f;

    const float* Abase = A  + (size_t)(bm0 + a_row) * K + a_c4;
    const float* Bbase = Bw + (size_t)b_row * NC + bn0 + b_c;

    float4 pa0, pa1, pb0, pb1;

    // prologue: tile 0
    pa0 = *(const float4*)(Abase);
    pa1 = *(const float4*)(Abase + (size_t)64 * K);
    pb0 = *(const float4*)(Bbase);
    pb1 = *(const float4*)(Bbase + (size_t)8 * NC);

    #pragma unroll 1
    for (int k0 = 0; k0 < K; k0 += 16) {
        const bool nxt = (k0 + 16) < K;

        // transform + stage current prefetch into smem buffer
        {
            const int buf = (k0 >> 4) & 1;
            if (AFF) {
                const float* sc = saff + k0 + a_c4;
                const float* sh = sc + K;
                pa0.x = fmaxf(fmaf(pa0.x, sc[0], sh[0]), 0.f);
                pa0.y = fmaxf(fmaf(pa0.y, sc[1], sh[1]), 0.f);
                pa0.z = fmaxf(fmaf(pa0.z, sc[2], sh[2]), 0.f);
                pa0.w = fmaxf(fmaf(pa0.w, sc[3], sh[3]), 0.f);
                pa1.x = fmaxf(fmaf(pa1.x, sc[0], sh[0]), 0.f);
                pa1.y = fmaxf(fmaf(pa1.y, sc[1], sh[1]), 0.f);
                pa1.z = fmaxf(fmaf(pa1.z, sc[2], sh[2]), 0.f);
                pa1.w = fmaxf(fmaf(pa1.w, sc[3], sh[3]), 0.f);
            }
            float* as = smem + buf * 2112;
            as[(a_c4 + 0) * 132 + a_row] = pa0.x;
            as[(a_c4 + 1) * 132 + a_row] = pa0.y;
            as[(a_c4 + 2) * 132 + a_row] = pa0.z;
            as[(a_c4 + 3) * 132 + a_row] = pa0.w;
            as[(a_c4 + 0) * 132 + a_row + 64] = pa1.x;
            as[(a_c4 + 1) * 132 + a_row + 64] = pa1.y;
            as[(a_c4 + 2) * 132 + a_row + 64] = pa1.z;
            as[(a_c4 + 3) * 132 + a_row + 64] = pa1.w;
            float* bs = smem + 4224 + buf * 2048;
            *(float4*)(bs + b_row * 128 + b_c) = pb0;
            *(float4*)(bs + (b_row + 8) * 128 + b_c) = pb1;
        }
        __syncthreads();

        // prefetch next tile from global
        if (nxt) {
            pa0 = *(const float4*)(Abase + k0 + 16);
            pa1 = *(const float4*)(Abase + (size_t)64 * K + k0 + 16);
            pb0 = *(const float4*)(Bbase + (size_t)(k0 + 16) * NC);
            pb1 = *(const float4*)(Bbase + (size_t)(k0 + 24) * NC);
        }

        // compute on current buffer
        {
            const int buf = (k0 >> 4) & 1;
            const float* as = smem + buf * 2112;
            const float* bs = smem + 4224 + buf * 2048;
            #pragma unroll
            for (int kk = 0; kk < 16; kk++) {
                float ar[8], br[8];
                *(float4*)&ar[0] = *(const float4*)(as + kk * 132 + ty * 8);
                *(float4*)&ar[4] = *(const float4*)(as + kk * 132 + ty * 8 + 4);
                *(float4*)&br[0] = *(const float4*)(bs + kk * 128 + tx * 8);
                *(float4*)&br[4] = *(const float4*)(bs + kk * 128 + tx * 8 + 4);
                #pragma unroll
                for (int m = 0; m < 8; m++)
                    #pragma unroll
                    for (int n = 0; n < 8; n++)
                        acc[m][n] = fmaf(ar[m], br[n], acc[m][n]);
            }
        }
        // next iteration stores into buf^1 — no hazard with lagging readers of buf
    }

    // epilogue: bias add, store, per-column stats (masked to real rows)
    float bcol[8];
    *(float4*)&bcol[0] = *(const float4*)(bias + bn0 + tx * 8);
    *(float4*)&bcol[4] = *(const float4*)(bias + bn0 + tx * 8 + 4);

    float psum[8], psq[8];
    #pragma unroll
    for (int n = 0; n < 8; n++) { psum[n] = 0.f; psq[n] = 0.f; }

    #pragma unroll
    for (int m = 0; m < 8; m++) {
        int row = bm0 + ty * 8 + m;
        float v[8];
        #pragma unroll
        for (int n = 0; n < 8; n++) v[n] = acc[m][n] + bcol[n];
        *(float4*)(C + (size_t)row * NC + bn0 + tx * 8)     = *(float4*)&v[0];
        *(float4*)(C + (size_t)row * NC + bn0 + tx * 8 + 4) = *(float4*)&v[4];
        if (row < NNODES) {
            #pragma unroll
            for (int n = 0; n < 8; n++) { psum[n] += v[n]; psq[n] += v[n] * v[n]; }
        }
    }

    __syncthreads();                       // main-loop smem reads done; safe to alias
    float* ssum = smem;                    // [16][128]
    float* ssq  = smem + 2048;             // [16][128]
    #pragma unroll
    for (int n = 0; n < 8; n++) {
        ssum[ty * 128 + tx * 8 + n] = psum[n];
        ssq [ty * 128 + tx * 8 + n] = psq[n];
    }
    __syncthreads();
    if (tid < 128) {
        float s = 0.f, q = 0.f;
        #pragma unroll
        for (int i = 0; i < 16; i++) { s += ssum[i * 128 + tid]; q += ssq[i * 128 + tid]; }
        atomicAdd(gsum + bn0 + tid, s);
        atomicAdd(gsq  + bn0 + tid, q);
    }
}

// ---------------- BN stats -> affine (scale, shift) ----------------
__global__ void k_finalize(const float* __restrict__ gsum, const float* __restrict__ gsq,
                           const float* __restrict__ gamma, const float* __restrict__ beta,
                           float* __restrict__ aff, int ncols) {
    int c = threadIdx.x;
    if (c >= ncols) return;
    const float invn = 1.0f / (float)NNODES;
    float mu  = gsum[c] * invn;
    float var = fmaxf(gsq[c] * invn - mu * mu, 0.f);
    float sc  = rsqrtf(var + 1e-5f) * gamma[c];
    aff[c]         = sc;
    aff[ncols + c] = beta[c] - mu * sc;
}

// ---------------- apply BN2 (+optional ReLU): h = bn(z2); z = h ----------------
__global__ void k_bnapply(int relu) {
    int i = blockIdx.x * blockDim.x + threadIdx.x;
    if (i >= NNODES * 32) return;
    int n = i >> 5, c = (i & 31) * 4;
    float4 v  = *(const float4*)(g_z + (size_t)n * DIM + c);
    float4 sc = *(const float4*)(g_aff2 + c);
    float4 sh = *(const float4*)(g_aff2 + DIM + c);
    v.x = fmaf(v.x, sc.x, sh.x);
    v.y = fmaf(v.y, sc.y, sh.y);
    v.z = fmaf(v.z, sc.z, sh.z);
    v.w = fmaf(v.w, sc.w, sh.w);
    if (relu) {
        v.x = fmaxf(v.x, 0.f); v.y = fmaxf(v.y, 0.f);
        v.z = fmaxf(v.z, 0.f); v.w = fmaxf(v.w, 0.f);
    }
    *(float4*)(g_h + (size_t)n * DIM + c) = v;
    *(float4*)(g_z + (size_t)n * DIM + c) = v;
}

// ---------------- output: zero xpool region ----------------
__global__ void k_zero_out(float* __restrict__ out) {
    int i = blockIdx.x * blockDim.x + threadIdx.x;
    if (i < NGRAPH * DIM) out[i] = 0.f;
}

// ---------------- output: xpool = segment_sum(h, batch); copy h ----------------
__global__ void k_pool(const int* __restrict__ batch, float* __restrict__ out) {
    int i = blockIdx.x * blockDim.x + threadIdx.x;
    if (i >= NNODES * 32) return;
    int n = i >> 5, c = (i & 31) * 4;
    float4 v = *(const float4*)(g_h + (size_t)n * DIM + c);
    *(float4*)(out + (size_t)NGRAPH * DIM + (size_t)n * DIM + c) = v;   // h output
    int b = __ldg(batch + n);
    red_add_v4(out + (size_t)b * DIM + c, v);
}

// ---------------- launch ----------------
extern "C" void kernel_launch(void* const* d_in, const int* in_sizes, int n_in,
                              void* d_out, int out_size) {
    const int*   batch    = (const int*)  d_in[0];
    const int*   x        = (const int*)  d_in[1];
    const int*   eidx     = (const int*)  d_in[2];
    const int*   eattr    = (const int*)  d_in[3];
    const float* atom_emb = (const float*)d_in[4];
    const float* bond_emb = (const float*)d_in[5];
    const float* W1       = (const float*)d_in[6];
    const float* b1       = (const float*)d_in[7];
    const float* g1       = (const float*)d_in[8];
    const float* be1      = (const float*)d_in[9];
    const float* W2       = (const float*)d_in[10];
    const float* b2       = (const float*)d_in[11];
    const float* gbn      = (const float*)d_in[12];
    const float* bbn      = (const float*)d_in[13];
    float* out = (float*)d_out;

    float *p_z, *p_z1, *p_sum1, *p_sq1, *p_aff1, *p_sum2, *p_sq2, *p_aff2;
    cudaGetSymbolAddress((void**)&p_z,    g_z);
    cudaGetSymbolAddress((void**)&p_z1,   g_z1);
    cudaGetSymbolAddress((void**)&p_sum1, g_sum1);
    cudaGetSymbolAddress((void**)&p_sq1,  g_sq1);
    cudaGetSymbolAddress((void**)&p_aff1, g_aff1);
    cudaGetSymbolAddress((void**)&p_sum2, g_sum2);
    cudaGetSymbolAddress((void**)&p_sq2,  g_sq2);
    cudaGetSymbolAddress((void**)&p_aff2, g_aff2);

    const int* src = eidx;
    const int* dst = eidx + NEDGE;

    const int ELEM_GRID = (NNODES * 32 + 255) / 256;

    k_init<<<ELEM_GRID, 256>>>(x, atom_emb);

    for (int i = 0; i < NLAYERS; i++) {
        k_zero_stats<<<1, 256>>>();
        k_scatter<<<(NEDGE + 7) / 8, 256>>>(src, dst, eattr, bond_emb);
        k_gemm<DIM, DIM2, false><<<dim3(NPAD / 128, DIM2 / 128), 256>>>(
            p_z, W1 + (size_t)i * DIM * DIM2, b1 + (size_t)i * DIM2, nullptr,
            p_z1, p_sum1, p_sq1);
        k_finalize<<<1, DIM2>>>(p_sum1, p_sq1, g1 + (size_t)i * DIM2, be1 + (size_t)i * DIM2,
                                p_aff1, DIM2);
        k_gemm<DIM2, DIM, true><<<dim3(NPAD / 128, DIM / 128), 256>>>(
            p_z1, W2 + (size_t)i * DIM2 * DIM, b2 + (size_t)i * DIM, p_aff1,
            p_z, p_sum2, p_sq2);
        k_finalize<<<1, DIM>>>(p_sum2, p_sq2, gbn + (size_t)i * DIM, bbn + (size_t)i * DIM,
                               p_aff2, DIM);
        k_bnapply<<<ELEM_GRID, 256>>>(i < NLAYERS - 1 ? 1 : 0);
    }

    k_zero_out<<<(NGRAPH * DIM + 255) / 256, 256>>>(out);
    k_pool<<<ELEM_GRID, 256>>>(batch, out);
}